// round 4
// baseline (speedup 1.0000x reference)
#include <cuda_runtime.h>
#include <mma.h>
using namespace nvcuda;

// ---------------------------------------------------------------------------
// Swin window-attention block, B=4, C=192, H=W=256, WS=8, SS=4, heads=8, hd=24
// ---------------------------------------------------------------------------

#define TOKENS 262144          // 4*256*256
#define CDIM   192

// Scratch (device globals; no allocation at launch time)
__device__ float g_xh  [50331648];   // shortcut, NHWC spatial order   [tok,192]
__device__ float g_h   [50331648];   // LN'd / reused buffer           [tok,192]
__device__ float g_qkv [150994944];  // qkv, window-token order        [tok,576]
__device__ float g_attn[50331648];   // attention out, window order    [tok,192]
__device__ float g_xh2 [50331648];   // x + attn, spatial order        [tok,192]
__device__ float g_mlp [201326592];  // gelu(fc1), spatial order       [tok,768]

enum { EPI_BIAS = 0, EPI_GELU = 1, EPI_PROJ = 2, EPI_FC2 = 3 };

// ---------------------------------------------------------------------------
// K1: NCHW -> NHWC transpose + LayerNorm1 + roll(-4,-4) + window partition
// grid (8, 256, 4) : (w-tile of 32, h, b), 256 threads
// ---------------------------------------------------------------------------
__global__ __launch_bounds__(256) void k_pre(
    const float* __restrict__ x, const float* __restrict__ gam,
    const float* __restrict__ bet, float* __restrict__ xh,
    float* __restrict__ hout)
{
    __shared__ float tile[192][33];
    __shared__ float mean_s[32], rstd_s[32];
    int w0 = blockIdx.x * 32, hh = blockIdx.y, b = blockIdx.z;
    int tid = threadIdx.x;

    const float* xb = x + ((size_t)b * 192 * 256 + hh) * 256 + w0;
    for (int idx = tid; idx < 192 * 32; idx += 256) {
        int c = idx >> 5, wl = idx & 31;
        tile[c][wl] = xb[(size_t)c * 65536 + wl];
    }
    __syncthreads();

    {   // 8 threads per spatial token compute LN stats
        int wl = tid >> 3, j = tid & 7;
        float s = 0.f, s2 = 0.f;
        for (int c = j; c < 192; c += 8) { float v = tile[c][wl]; s += v; s2 += v * v; }
        #pragma unroll
        for (int o = 4; o > 0; o >>= 1) {
            s  += __shfl_xor_sync(0xffffffffu, s,  o, 8);
            s2 += __shfl_xor_sync(0xffffffffu, s2, o, 8);
        }
        if (j == 0) {
            float m = s * (1.f / 192.f);
            float var = s2 * (1.f / 192.f) - m * m;
            mean_s[wl] = m;
            rstd_s[wl] = rsqrtf(var + 1e-5f);
        }
    }
    __syncthreads();

    int ir = (hh - 4) & 255;           // rolled row
    for (int idx = tid; idx < 192 * 32; idx += 256) {
        int wl = idx / 192, c = idx - wl * 192;
        int w = w0 + wl;
        float v = tile[c][wl];
        int sp = (b * 256 + hh) * 256 + w;
        xh[(size_t)sp * 192 + c] = v;
        float vn = (v - mean_s[wl]) * rstd_s[wl] * gam[c] + bet[c];
        int jr = (w - 4) & 255;        // rolled col
        int t = ((b * 32 + (ir >> 3)) * 32 + (jr >> 3)) * 64 + ((ir & 7) * 8 + (jr & 7));
        hout[(size_t)t * 192 + c] = vn;
    }
}

// ---------------------------------------------------------------------------
// tf32 WMMA GEMM: C[M,N] = A[M,K] @ W[K,N] + bias, with fused epilogues.
// BM=128, BN=64, BK=16; 8 warps (4m x 2n), each warp 32x32 via 2x2 m16n16k8.
// grid (N/64, M/128), 256 threads. M,N,K all divisible by tile sizes here.
// ---------------------------------------------------------------------------
template<int EPI>
__global__ __launch_bounds__(256)
void gemm_tf32(const float* __restrict__ A, const float* __restrict__ W,
               const float* __restrict__ bias, float* __restrict__ C,
               int N, int K, const float* __restrict__ res)
{
    __shared__ __align__(16) char smembuf[34816];
    float (*As)[24] = reinterpret_cast<float(*)[24]>(smembuf);            // 128x24 = 12288B
    float (*Bs)[68] = reinterpret_cast<float(*)[68]>(smembuf + 12288);    // 16x68  =  4352B
    float (*Cs)[68] = reinterpret_cast<float(*)[68]>(smembuf);            // 128x68 = 34816B (reuse)

    int tid = threadIdx.x;
    int mBase = blockIdx.y * 128, nBase = blockIdx.x * 64;
    int warp = tid >> 5, wm = warp >> 1, wn = warp & 1;

    wmma::fragment<wmma::accumulator, 16, 16, 8, float> acc[2][2];
    #pragma unroll
    for (int i = 0; i < 2; i++)
        #pragma unroll
        for (int j = 0; j < 2; j++)
            wmma::fill_fragment(acc[i][j], 0.f);

    for (int k0 = 0; k0 < K; k0 += 16) {
        #pragma unroll
        for (int u = 0; u < 2; u++) {          // A tile: 128x16, 2 float4/thread
            int f = tid * 2 + u;
            int r = f >> 2, s = f & 3;
            *(float4*)&As[r][s * 4] =
                *(const float4*)&A[(size_t)(mBase + r) * K + k0 + s * 4];
        }
        {                                      // B tile: 16x64, 1 float4/thread
            int r = tid >> 4, s = tid & 15;
            *(float4*)&Bs[r][s * 4] =
                *(const float4*)&W[(size_t)(k0 + r) * N + nBase + s * 4];
        }
        __syncthreads();

        #pragma unroll
        for (int kk = 0; kk < 16; kk += 8) {
            wmma::fragment<wmma::matrix_a, 16, 16, 8, wmma::precision::tf32, wmma::row_major> af[2];
            wmma::fragment<wmma::matrix_b, 16, 16, 8, wmma::precision::tf32, wmma::row_major> bf[2];
            wmma::load_matrix_sync(af[0], &As[wm * 32][kk], 24);
            wmma::load_matrix_sync(af[1], &As[wm * 32 + 16][kk], 24);
            wmma::load_matrix_sync(bf[0], &Bs[kk][wn * 32], 68);
            wmma::load_matrix_sync(bf[1], &Bs[kk][wn * 32 + 16], 68);
            #pragma unroll
            for (int e = 0; e < af[0].num_elements; e++) {
                af[0].x[e] = wmma::__float_to_tf32(af[0].x[e]);
                af[1].x[e] = wmma::__float_to_tf32(af[1].x[e]);
            }
            #pragma unroll
            for (int e = 0; e < bf[0].num_elements; e++) {
                bf[0].x[e] = wmma::__float_to_tf32(bf[0].x[e]);
                bf[1].x[e] = wmma::__float_to_tf32(bf[1].x[e]);
            }
            #pragma unroll
            for (int i = 0; i < 2; i++)
                #pragma unroll
                for (int j = 0; j < 2; j++)
                    wmma::mma_sync(acc[i][j], af[i], bf[j], acc[i][j]);
        }
        __syncthreads();
    }

    #pragma unroll
    for (int i = 0; i < 2; i++)
        #pragma unroll
        for (int j = 0; j < 2; j++)
            wmma::store_matrix_sync(&Cs[wm * 32 + i * 16][wn * 32 + j * 16],
                                    acc[i][j], 68, wmma::mem_row_major);
    __syncthreads();

    for (int idx = tid; idx < 128 * 64; idx += 256) {
        int lr = idx >> 6, lc = idx & 63;
        int row = mBase + lr, col = nBase + lc;
        float vv = Cs[lr][lc] + bias[col];
        if constexpr (EPI == EPI_GELU) {
            vv = 0.5f * vv * (1.f + erff(vv * 0.70710678118654752f));
            C[(size_t)row * N + col] = vv;
        } else if constexpr (EPI == EPI_PROJ) {
            // window-order row -> spatial (un-roll +4,+4), add shortcut
            int win = row >> 6, n = row & 63;
            int bb = win >> 10, wi = (win >> 5) & 31, wj = win & 31;
            int irr = wi * 8 + (n >> 3), jrr = wj * 8 + (n & 7);
            int i2 = (irr + 4) & 255, j2 = (jrr + 4) & 255;
            int sp = (bb * 256 + i2) * 256 + j2;
            vv += res[(size_t)sp * 192 + col];
            C[(size_t)sp * 192 + col] = vv;
        } else if constexpr (EPI == EPI_FC2) {
            vv += res[(size_t)row * 192 + col];
            C[(size_t)row * 192 + col] = vv;
        } else {
            C[(size_t)row * N + col] = vv;
        }
    }
}

// ---------------------------------------------------------------------------
// K3: fused window attention. grid (4096 windows, 8 heads), 128 threads.
// fp32 SIMT: QK^T (register-tiled 4x8), +rel-pos-bias +shift mask, softmax, AV.
// ---------------------------------------------------------------------------
__global__ __launch_bounds__(128) void k_attn(
    const float* __restrict__ qkv, const float* __restrict__ rpb,
    float* __restrict__ out)
{
    __shared__ float q[64][25], kt[64][25], vt[64][25];
    __shared__ float S[64][65];
    __shared__ float rpb_s[225];
    __shared__ int cnt[64];

    int win = blockIdx.x, head = blockIdx.y, tid = threadIdx.x;

    for (int i = tid; i < 225; i += 128) rpb_s[i] = rpb[i * 8 + head];
    if (tid < 64) {
        int wi = (win >> 5) & 31, wj = win & 31;
        int ir = wi * 8 + (tid >> 3), jr = wj * 8 + (tid & 7);
        int gi = ir < 248 ? 0 : (ir < 252 ? 1 : 2);
        int gj = jr < 248 ? 0 : (jr < 252 ? 1 : 2);
        cnt[tid] = gi * 3 + gj;
    }

    const float scale = 0.20412414523193154f;   // 24^-0.5
    int base = win * 64 * 576 + head * 24;
    for (int idx = tid; idx < 64 * 24; idx += 128) {
        int n = idx / 24, d = idx - n * 24;
        int o = base + n * 576 + d;
        q[n][d]  = qkv[o] * scale;
        kt[n][d] = qkv[o + 192];
        vt[n][d] = qkv[o + 384];
    }
    __syncthreads();

    // scores: thread (tr,tc) computes rows {tr,tr+16,tr+32,tr+48} x cols [tc*8, tc*8+8)
    int tr = tid >> 3, tc = tid & 7;
    float acc[4][8];
    #pragma unroll
    for (int i = 0; i < 4; i++)
        #pragma unroll
        for (int j = 0; j < 8; j++) acc[i][j] = 0.f;

    for (int d = 0; d < 24; d++) {
        float qv[4], kv[8];
        #pragma unroll
        for (int i = 0; i < 4; i++) qv[i] = q[tr + 16 * i][d];
        #pragma unroll
        for (int j = 0; j < 8; j++) kv[j] = kt[tc * 8 + j][d];
        #pragma unroll
        for (int i = 0; i < 4; i++)
            #pragma unroll
            for (int j = 0; j < 8; j++) acc[i][j] += qv[i] * kv[j];
    }
    #pragma unroll
    for (int i = 0; i < 4; i++) {
        int r = tr + 16 * i, rr = r >> 3, rc = r & 7;
        #pragma unroll
        for (int j = 0; j < 8; j++) {
            int c = tc * 8 + j, cr = c >> 3, cc = c & 7;
            float bv = rpb_s[(rr - cr + 7) * 15 + (rc - cc + 7)];
            float mv = (cnt[r] != cnt[c]) ? -100.f : 0.f;
            S[r][c] = acc[i][j] + bv + mv;
        }
    }
    __syncthreads();

    // softmax: 2 threads per row
    {
        int row = tid >> 1, c0 = (tid & 1) * 32;
        float mx = -1e30f;
        #pragma unroll
        for (int j2 = 0; j2 < 32; j2++) mx = fmaxf(mx, S[row][c0 + j2]);
        mx = fmaxf(mx, __shfl_xor_sync(0xffffffffu, mx, 1));
        float sum = 0.f;
        #pragma unroll
        for (int j2 = 0; j2 < 32; j2++) {
            float e = __expf(S[row][c0 + j2] - mx);
            S[row][c0 + j2] = e;
            sum += e;
        }
        sum += __shfl_xor_sync(0xffffffffu, sum, 1);
        float inv = 1.f / sum;
        #pragma unroll
        for (int j2 = 0; j2 < 32; j2++) S[row][c0 + j2] *= inv;
    }
    __syncthreads();

    // AV: 2 threads per row, 12 head-dims each
    {
        int n = tid >> 1, d0 = (tid & 1) * 12;
        float o[12];
        #pragma unroll
        for (int dd = 0; dd < 12; dd++) o[dd] = 0.f;
        for (int m = 0; m < 64; m++) {
            float p = S[n][m];
            #pragma unroll
            for (int dd = 0; dd < 12; dd++) o[dd] += p * vt[m][d0 + dd];
        }
        int ob = (win * 64 + n) * 192 + head * 24 + d0;
        #pragma unroll
        for (int dd = 0; dd < 12; dd++) out[ob + dd] = o[dd];
    }
}

// ---------------------------------------------------------------------------
// K5: LayerNorm2 (one warp per token). grid 32768, 256 threads (8 rows/block).
// ---------------------------------------------------------------------------
__global__ __launch_bounds__(256) void k_ln(
    const float* __restrict__ in, const float* __restrict__ gam,
    const float* __restrict__ bet, float* __restrict__ out)
{
    int warp = threadIdx.x >> 5, lane = threadIdx.x & 31;
    int row = blockIdx.x * 8 + warp;
    const float* r = in + (size_t)row * 192;
    float v[6];
    float s = 0.f, s2 = 0.f;
    #pragma unroll
    for (int i = 0; i < 6; i++) {
        v[i] = r[lane + 32 * i];
        s += v[i]; s2 += v[i] * v[i];
    }
    #pragma unroll
    for (int o = 16; o > 0; o >>= 1) {
        s  += __shfl_xor_sync(0xffffffffu, s,  o);
        s2 += __shfl_xor_sync(0xffffffffu, s2, o);
    }
    float m = s * (1.f / 192.f);
    float rstd = rsqrtf(s2 * (1.f / 192.f) - m * m + 1e-5f);
    float* o = out + (size_t)row * 192;
    #pragma unroll
    for (int i = 0; i < 6; i++) {
        int c = lane + 32 * i;
        o[c] = (v[i] - m) * rstd * gam[c] + bet[c];
    }
}

// ---------------------------------------------------------------------------
// K8: NHWC -> NCHW transpose to d_out. grid (8, 256, 4), 256 threads.
// ---------------------------------------------------------------------------
__global__ __launch_bounds__(256) void k_post(
    const float* __restrict__ in, float* __restrict__ out)
{
    __shared__ float t2[32][193];
    int w0 = blockIdx.x * 32, hh = blockIdx.y, b = blockIdx.z, tid = threadIdx.x;
    const float* ib = in + ((size_t)(b * 256 + hh) * 256 + w0) * 192;
    for (int idx = tid; idx < 6144; idx += 256) {
        int wl = idx / 192, c = idx - wl * 192;
        t2[wl][c] = ib[(size_t)wl * 192 + c];
    }
    __syncthreads();
    float* ob = out + (size_t)b * 192 * 65536 + hh * 256 + w0;
    for (int idx = tid; idx < 6144; idx += 256) {
        int c = idx >> 5, wl = idx & 31;
        ob[(size_t)c * 65536 + wl] = t2[wl][c];
    }
}

// ---------------------------------------------------------------------------
extern "C" void kernel_launch(void* const* d_in, const int* in_sizes, int n_in,
                              void* d_out, int out_size)
{
    const float* x     = (const float*)d_in[0];
    const float* n1g   = (const float*)d_in[1];
    const float* n1b   = (const float*)d_in[2];
    const float* qkvw  = (const float*)d_in[3];
    const float* qkvb  = (const float*)d_in[4];
    const float* projw = (const float*)d_in[5];
    const float* projb = (const float*)d_in[6];
    const float* rpb   = (const float*)d_in[7];
    const float* n2g   = (const float*)d_in[8];
    const float* n2b   = (const float*)d_in[9];
    const float* fc1w  = (const float*)d_in[10];
    const float* fc1b  = (const float*)d_in[11];
    const float* fc2w  = (const float*)d_in[12];
    const float* fc2b  = (const float*)d_in[13];

    float *xh, *h, *qkv, *attn, *xh2, *mlp;
    cudaGetSymbolAddress((void**)&xh,   g_xh);
    cudaGetSymbolAddress((void**)&h,    g_h);
    cudaGetSymbolAddress((void**)&qkv,  g_qkv);
    cudaGetSymbolAddress((void**)&attn, g_attn);
    cudaGetSymbolAddress((void**)&xh2,  g_xh2);
    cudaGetSymbolAddress((void**)&mlp,  g_mlp);

    // 1. transpose + LN1 + roll + window partition
    k_pre<<<dim3(8, 256, 4), 256>>>(x, n1g, n1b, xh, h);
    // 2. QKV GEMM (tf32)
    gemm_tf32<EPI_BIAS><<<dim3(9, 2048), 256>>>(h, qkvw, qkvb, qkv, 576, 192, nullptr);
    // 3. window attention
    k_attn<<<dim3(4096, 8), 128>>>(qkv, rpb, attn);
    // 4. proj GEMM + window reverse + unroll + residual
    gemm_tf32<EPI_PROJ><<<dim3(3, 2048), 256>>>(attn, projw, projb, xh2, 192, 192, xh);
    // 5. LN2
    k_ln<<<32768, 256>>>(xh2, n2g, n2b, h);
    // 6. fc1 + GELU
    gemm_tf32<EPI_GELU><<<dim3(12, 2048), 256>>>(h, fc1w, fc1b, mlp, 768, 192, nullptr);
    // 7. fc2 + residual
    gemm_tf32<EPI_FC2><<<dim3(3, 2048), 256>>>(mlp, fc2w, fc2b, h, 192, 768, xh2);
    // 8. NHWC -> NCHW output
    k_post<<<dim3(8, 256, 4), 256>>>(h, (float*)d_out);
}

// round 7
// speedup vs baseline: 2.7290x; 2.7290x over previous
#include <cuda_runtime.h>
#include <cuda_bf16.h>
#include <cuda_pipeline.h>
#include <mma.h>
using namespace nvcuda;

// ---------------------------------------------------------------------------
// Swin window-attention block, B=4, C=192, H=W=256, WS=8, SS=4, heads=8, hd=24
// bf16 tensor-core GEMMs (fp32 residual path), double-buffered cp.async.
// ---------------------------------------------------------------------------

// Scratch (device globals; no allocation at launch time)
__device__ __align__(128) float         g_xh  [50331648];   // shortcut (fp32), NHWC spatial
__device__ __align__(128) float         g_xh2 [50331648];   // x + attn (fp32), NHWC spatial
__device__ __align__(128) __nv_bfloat16 g_h   [50331648];   // LN'd activations (bf16)
__device__ __align__(128) __nv_bfloat16 g_qkv [150994944];  // qkv (bf16), window-token order
__device__ __align__(128) __nv_bfloat16 g_attn[50331648];   // attn out (bf16), window order
__device__ __align__(128) __nv_bfloat16 g_mlp [201326592];  // gelu(fc1) (bf16)
__device__ __align__(128) __nv_bfloat16 g_wq  [110592];
__device__ __align__(128) __nv_bfloat16 g_wp  [36864];
__device__ __align__(128) __nv_bfloat16 g_w1  [147456];
__device__ __align__(128) __nv_bfloat16 g_w2  [147456];

enum { EPI_QKV = 0, EPI_GELU = 1, EPI_PROJ = 2, EPI_FC2 = 3 };

// ---------------------------------------------------------------------------
// weight fp32 -> bf16 convert
// ---------------------------------------------------------------------------
__global__ __launch_bounds__(256) void k_cvt(
    const float* __restrict__ s, __nv_bfloat16* __restrict__ d, int n)
{
    int i = blockIdx.x * 256 + threadIdx.x;
    if (i < n) d[i] = __float2bfloat16(s[i]);
}

// ---------------------------------------------------------------------------
// K1: NCHW -> NHWC + LayerNorm1 + roll(-4,-4) + window partition (bf16 out)
// grid (8, 256, 4), 256 threads
// ---------------------------------------------------------------------------
__global__ __launch_bounds__(256) void k_pre(
    const float* __restrict__ x, const float* __restrict__ gam,
    const float* __restrict__ bet, float* __restrict__ xh,
    __nv_bfloat16* __restrict__ hout)
{
    __shared__ float tile[192][33];
    __shared__ float mean_s[32], rstd_s[32];
    int w0 = blockIdx.x * 32, hh = blockIdx.y, b = blockIdx.z;
    int tid = threadIdx.x;

    const float* xb = x + ((size_t)b * 192 * 256 + hh) * 256 + w0;
    for (int idx = tid; idx < 192 * 32; idx += 256) {
        int c = idx >> 5, wl = idx & 31;
        tile[c][wl] = xb[(size_t)c * 65536 + wl];
    }
    __syncthreads();

    {   // 8 threads per spatial token: LN stats
        int wl = tid >> 3, j = tid & 7;
        float s = 0.f, s2 = 0.f;
        for (int c = j; c < 192; c += 8) { float v = tile[c][wl]; s += v; s2 += v * v; }
        #pragma unroll
        for (int o = 4; o > 0; o >>= 1) {
            s  += __shfl_xor_sync(0xffffffffu, s,  o, 8);
            s2 += __shfl_xor_sync(0xffffffffu, s2, o, 8);
        }
        if (j == 0) {
            float m = s * (1.f / 192.f);
            mean_s[wl] = m;
            rstd_s[wl] = rsqrtf(s2 * (1.f / 192.f) - m * m + 1e-5f);
        }
    }
    __syncthreads();

    int ir = (hh - 4) & 255;
    for (int idx = tid; idx < 192 * 32; idx += 256) {
        int wl = idx / 192, c = idx - wl * 192;
        int w = w0 + wl;
        float v = tile[c][wl];
        int sp = (b * 256 + hh) * 256 + w;
        xh[(size_t)sp * 192 + c] = v;
        float vn = (v - mean_s[wl]) * rstd_s[wl] * gam[c] + bet[c];
        int jr = (w - 4) & 255;
        int t = ((b * 32 + (ir >> 3)) * 32 + (jr >> 3)) * 64 + ((ir & 7) * 8 + (jr & 7));
        hout[(size_t)t * 192 + c] = __float2bfloat16(vn);
    }
}

// ---------------------------------------------------------------------------
// bf16 WMMA GEMM: C[M,N] = A[M,K] @ W[K,N] + bias, fused epilogues.
// BM=128, BN=64, BK=32; 8 warps (4m x 2n), warp tile 32x32 via 2x2 m16n16k16.
// Double-buffered cp.async. grid (N/64, M/128), 256 threads.
// ---------------------------------------------------------------------------
template<int EPI>
__global__ __launch_bounds__(256, 2)
void gemm_bf16(const __nv_bfloat16* __restrict__ A, const __nv_bfloat16* __restrict__ W,
               const float* __restrict__ bias, void* __restrict__ Cout,
               int N, int K, const float* __restrict__ res)
{
    __shared__ __align__(16) char sm[34816];
    auto As = reinterpret_cast<__nv_bfloat16(*)[128][40]>(sm);          // [2][128][40] = 20480B
    auto Bs = reinterpret_cast<__nv_bfloat16(*)[32][72]>(sm + 20480);   // [2][32][72]  =  9216B
    float (*Cs)[68] = reinterpret_cast<float(*)[68]>(sm);               // epilogue reuse 34816B

    const int tid = threadIdx.x;
    const int mBase = blockIdx.y * 128, nBase = blockIdx.x * 64;
    const int warp = tid >> 5, wm = warp >> 1, wn = warp & 1;

    wmma::fragment<wmma::accumulator, 16, 16, 16, float> acc[2][2];
    #pragma unroll
    for (int i = 0; i < 2; i++)
        #pragma unroll
        for (int j = 0; j < 2; j++) wmma::fill_fragment(acc[i][j], 0.f);

    const int nk = K >> 5;

    auto load_tile = [&](int buf, int k0) {
        int f = tid << 1;
        {
            int r = f >> 2, c = (f & 3) << 3;
            __pipeline_memcpy_async(&As[buf][r][c],
                                    &A[(size_t)(mBase + r) * K + k0 + c], 16);
        }
        {
            int r = (f + 1) >> 2, c = ((f + 1) & 3) << 3;
            __pipeline_memcpy_async(&As[buf][r][c],
                                    &A[(size_t)(mBase + r) * K + k0 + c], 16);
        }
        {
            int r = tid >> 3, c = (tid & 7) << 3;
            __pipeline_memcpy_async(&Bs[buf][r][c],
                                    &W[(size_t)(k0 + r) * N + nBase + c], 16);
        }
    };

    load_tile(0, 0);
    __pipeline_commit();

    for (int it = 0; it < nk; ++it) {
        if (it + 1 < nk) { load_tile((it + 1) & 1, (it + 1) << 5); __pipeline_commit(); }
        __pipeline_wait_prior((it + 1 < nk) ? 1 : 0);
        __syncthreads();
        int buf = it & 1;
        #pragma unroll
        for (int kk = 0; kk < 2; ++kk) {
            wmma::fragment<wmma::matrix_a, 16, 16, 16, __nv_bfloat16, wmma::row_major> af[2];
            wmma::fragment<wmma::matrix_b, 16, 16, 16, __nv_bfloat16, wmma::row_major> bf[2];
            wmma::load_matrix_sync(af[0], &As[buf][wm * 32][kk * 16], 40);
            wmma::load_matrix_sync(af[1], &As[buf][wm * 32 + 16][kk * 16], 40);
            wmma::load_matrix_sync(bf[0], &Bs[buf][kk * 16][wn * 32], 72);
            wmma::load_matrix_sync(bf[1], &Bs[buf][kk * 16][wn * 32 + 16], 72);
            #pragma unroll
            for (int i = 0; i < 2; i++)
                #pragma unroll
                for (int j = 0; j < 2; j++)
                    wmma::mma_sync(acc[i][j], af[i], bf[j], acc[i][j]);
        }
        __syncthreads();
    }

    #pragma unroll
    for (int i = 0; i < 2; i++)
        #pragma unroll
        for (int j = 0; j < 2; j++)
            wmma::store_matrix_sync(&Cs[wm * 32 + i * 16][wn * 32 + j * 16],
                                    acc[i][j], 68, wmma::mem_row_major);
    __syncthreads();

    if constexpr (EPI == EPI_FC2) {
        // pass 1 (row-major, coalesced res reads): add bias + residual in smem
        for (int idx = tid; idx < 128 * 64; idx += 256) {
            int lr = idx >> 6, lc = idx & 63;
            Cs[lr][lc] += bias[nBase + lc] + res[(size_t)(mBase + lr) * 192 + nBase + lc];
        }
        __syncthreads();
        // pass 2 (col-major): coalesced NCHW writes to d_out
        float* out = (float*)Cout;
        for (int idx = tid; idx < 128 * 64; idx += 256) {
            int lc = idx >> 7, lr = idx & 127;
            int row = mBase + lr, col = nBase + lc;
            int b = row >> 16, hw = row & 65535;
            out[((size_t)(b * 192 + col) << 16) + hw] = Cs[lr][lc];
        }
    } else {
        for (int idx = tid; idx < 128 * 64; idx += 256) {
            int lr = idx >> 6, lc = idx & 63;
            int row = mBase + lr, col = nBase + lc;
            float vv = Cs[lr][lc] + bias[col];
            if constexpr (EPI == EPI_GELU) {
                vv = 0.5f * vv * (1.f + erff(vv * 0.70710678118654752f));
                ((__nv_bfloat16*)Cout)[(size_t)row * N + col] = __float2bfloat16(vv);
            } else if constexpr (EPI == EPI_PROJ) {
                // window-order row -> spatial (un-roll +4,+4), add shortcut (fp32)
                int win = row >> 6, n = row & 63;
                int bb = win >> 10, wi = (win >> 5) & 31, wj = win & 31;
                int irr = wi * 8 + (n >> 3), jrr = wj * 8 + (n & 7);
                int i2 = (irr + 4) & 255, j2 = (jrr + 4) & 255;
                int sp = (bb * 256 + i2) * 256 + j2;
                vv += res[(size_t)sp * 192 + col];
                ((float*)Cout)[(size_t)sp * 192 + col] = vv;
            } else {  // EPI_QKV
                ((__nv_bfloat16*)Cout)[(size_t)row * N + col] = __float2bfloat16(vv);
            }
        }
    }
}

// ---------------------------------------------------------------------------
// K3: fused window attention. grid (4096 windows, 8 heads), 128 threads, fp32.
// ---------------------------------------------------------------------------
__global__ __launch_bounds__(128) void k_attn(
    const __nv_bfloat16* __restrict__ qkv, const float* __restrict__ rpb,
    __nv_bfloat16* __restrict__ out)
{
    __shared__ float q[64][25], kt[64][25], vt[64][25];
    __shared__ float S[64][65];
    __shared__ float rpb_s[225];
    __shared__ int cnt[64];

    int win = blockIdx.x, head = blockIdx.y, tid = threadIdx.x;

    for (int i = tid; i < 225; i += 128) rpb_s[i] = rpb[i * 8 + head];
    if (tid < 64) {
        int wi = (win >> 5) & 31, wj = win & 31;
        int ir = wi * 8 + (tid >> 3), jr = wj * 8 + (tid & 7);
        int gi = ir < 248 ? 0 : (ir < 252 ? 1 : 2);
        int gj = jr < 248 ? 0 : (jr < 252 ? 1 : 2);
        cnt[tid] = gi * 3 + gj;
    }

    const float scale = 0.20412414523193154f;   // 24^-0.5
    int base = win * 64 * 576 + head * 24;
    for (int idx = tid; idx < 64 * 24; idx += 128) {
        int n = idx / 24, d = idx - n * 24;
        int o = base + n * 576 + d;
        q[n][d]  = __bfloat162float(qkv[o]) * scale;
        kt[n][d] = __bfloat162float(qkv[o + 192]);
        vt[n][d] = __bfloat162float(qkv[o + 384]);
    }
    __syncthreads();

    int tr = tid >> 3, tc = tid & 7;
    float acc[4][8];
    #pragma unroll
    for (int i = 0; i < 4; i++)
        #pragma unroll
        for (int j = 0; j < 8; j++) acc[i][j] = 0.f;

    for (int d = 0; d < 24; d++) {
        float qv[4], kv[8];
        #pragma unroll
        for (int i = 0; i < 4; i++) qv[i] = q[tr + 16 * i][d];
        #pragma unroll
        for (int j = 0; j < 8; j++) kv[j] = kt[tc * 8 + j][d];
        #pragma unroll
        for (int i = 0; i < 4; i++)
            #pragma unroll
            for (int j = 0; j < 8; j++) acc[i][j] += qv[i] * kv[j];
    }
    #pragma unroll
    for (int i = 0; i < 4; i++) {
        int r = tr + 16 * i, rr = r >> 3, rc = r & 7;
        #pragma unroll
        for (int j = 0; j < 8; j++) {
            int c = tc * 8 + j, cr = c >> 3, cc = c & 7;
            float bv = rpb_s[(rr - cr + 7) * 15 + (rc - cc + 7)];
            float mv = (cnt[r] != cnt[c]) ? -100.f : 0.f;
            S[r][c] = acc[i][j] + bv + mv;
        }
    }
    __syncthreads();

    {   // softmax: 2 threads per row
        int row = tid >> 1, c0 = (tid & 1) * 32;
        float mx = -1e30f;
        #pragma unroll
        for (int j2 = 0; j2 < 32; j2++) mx = fmaxf(mx, S[row][c0 + j2]);
        mx = fmaxf(mx, __shfl_xor_sync(0xffffffffu, mx, 1));
        float sum = 0.f;
        #pragma unroll
        for (int j2 = 0; j2 < 32; j2++) {
            float e = __expf(S[row][c0 + j2] - mx);
            S[row][c0 + j2] = e;
            sum += e;
        }
        sum += __shfl_xor_sync(0xffffffffu, sum, 1);
        float inv = 1.f / sum;
        #pragma unroll
        for (int j2 = 0; j2 < 32; j2++) S[row][c0 + j2] *= inv;
    }
    __syncthreads();

    {   // AV: 2 threads per row, 12 head-dims each
        int n = tid >> 1, d0 = (tid & 1) * 12;
        float o[12];
        #pragma unroll
        for (int dd = 0; dd < 12; dd++) o[dd] = 0.f;
        for (int m = 0; m < 64; m++) {
            float p = S[n][m];
            #pragma unroll
            for (int dd = 0; dd < 12; dd++) o[dd] += p * vt[m][d0 + dd];
        }
        int ob = (win * 64 + n) * 192 + head * 24 + d0;
        #pragma unroll
        for (int dd = 0; dd < 12; dd++) out[ob + dd] = __float2bfloat16(o[dd]);
    }
}

// ---------------------------------------------------------------------------
// K5: LayerNorm2 (one warp per token), bf16 out. grid 32768, 256 threads.
// ---------------------------------------------------------------------------
__global__ __launch_bounds__(256) void k_ln(
    const float* __restrict__ in, const float* __restrict__ gam,
    const float* __restrict__ bet, __nv_bfloat16* __restrict__ out)
{
    int warp = threadIdx.x >> 5, lane = threadIdx.x & 31;
    int row = blockIdx.x * 8 + warp;
    const float* r = in + (size_t)row * 192;
    float v[6];
    float s = 0.f, s2 = 0.f;
    #pragma unroll
    for (int i = 0; i < 6; i++) {
        v[i] = r[lane + 32 * i];
        s += v[i]; s2 += v[i] * v[i];
    }
    #pragma unroll
    for (int o = 16; o > 0; o >>= 1) {
        s  += __shfl_xor_sync(0xffffffffu, s,  o);
        s2 += __shfl_xor_sync(0xffffffffu, s2, o);
    }
    float m = s * (1.f / 192.f);
    float rstd = rsqrtf(s2 * (1.f / 192.f) - m * m + 1e-5f);
    __nv_bfloat16* o = out + (size_t)row * 192;
    #pragma unroll
    for (int i = 0; i < 6; i++) {
        int c = lane + 32 * i;
        o[c] = __float2bfloat16((v[i] - m) * rstd * gam[c] + bet[c]);
    }
}

// ---------------------------------------------------------------------------
extern "C" void kernel_launch(void* const* d_in, const int* in_sizes, int n_in,
                              void* d_out, int out_size)
{
    const float* x     = (const float*)d_in[0];
    const float* n1g   = (const float*)d_in[1];
    const float* n1b   = (const float*)d_in[2];
    const float* qkvw  = (const float*)d_in[3];
    const float* qkvb  = (const float*)d_in[4];
    const float* projw = (const float*)d_in[5];
    const float* projb = (const float*)d_in[6];
    const float* rpb   = (const float*)d_in[7];
    const float* n2g   = (const float*)d_in[8];
    const float* n2b   = (const float*)d_in[9];
    const float* fc1w  = (const float*)d_in[10];
    const float* fc1b  = (const float*)d_in[11];
    const float* fc2w  = (const float*)d_in[12];
    const float* fc2b  = (const float*)d_in[13];

    float *xh, *xh2;
    __nv_bfloat16 *h, *qkv, *attn, *mlp, *wq, *wp, *w1, *w2;
    cudaGetSymbolAddress((void**)&xh,   g_xh);
    cudaGetSymbolAddress((void**)&xh2,  g_xh2);
    cudaGetSymbolAddress((void**)&h,    g_h);
    cudaGetSymbolAddress((void**)&qkv,  g_qkv);
    cudaGetSymbolAddress((void**)&attn, g_attn);
    cudaGetSymbolAddress((void**)&mlp,  g_mlp);
    cudaGetSymbolAddress((void**)&wq,   g_wq);
    cudaGetSymbolAddress((void**)&wp,   g_wp);
    cudaGetSymbolAddress((void**)&w1,   g_w1);
    cudaGetSymbolAddress((void**)&w2,   g_w2);

    // 0. weight converts (tiny)
    k_cvt<<<(110592 + 255) / 256, 256>>>(qkvw, wq, 110592);
    k_cvt<<<(36864  + 255) / 256, 256>>>(projw, wp, 36864);
    k_cvt<<<(147456 + 255) / 256, 256>>>(fc1w,  w1, 147456);
    k_cvt<<<(147456 + 255) / 256, 256>>>(fc2w,  w2, 147456);

    // 1. transpose + LN1 + roll + window partition
    k_pre<<<dim3(8, 256, 4), 256>>>(x, n1g, n1b, xh, h);
    // 2. QKV GEMM
    gemm_bf16<EPI_QKV ><<<dim3(9, 2048),  256>>>(h,    wq, qkvb,  qkv,   576, 192, nullptr);
    // 3. window attention
    k_attn<<<dim3(4096, 8), 128>>>(qkv, rpb, attn);
    // 4. proj GEMM + window reverse + unroll + residual -> xh2 (fp32)
    gemm_bf16<EPI_PROJ><<<dim3(3, 2048),  256>>>(attn, wp, projb, xh2,   192, 192, xh);
    // 5. LN2 -> h (bf16)
    k_ln<<<32768, 256>>>(xh2, n2g, n2b, h);
    // 6. fc1 + GELU -> mlp (bf16)
    gemm_bf16<EPI_GELU><<<dim3(12, 2048), 256>>>(h,    w1, fc1b,  mlp,   768, 192, nullptr);
    // 7. fc2 + residual -> d_out (NCHW fp32, fused transpose)
    gemm_bf16<EPI_FC2 ><<<dim3(3, 2048),  256>>>(mlp,  w2, fc2b,  d_out, 192, 768, xh2);
}